// round 6
// baseline (speedup 1.0000x reference)
#include <cuda_runtime.h>
#include <cstdint>

typedef unsigned long long u64;
typedef unsigned int u32;

// ---------------- problem constants ----------------
#define BB 8
#define CC 256
#define NPOS 21824              // per-image positions across 5 maps
#define NANCH 196416            // NPOS * 9
#define NKEY 196608             // 24 * 8192 (padded)
#define KSEL 300
#define NCHUNK 24               // stage1 chunks of 8192 per image
#define NCAND (NCHUNK * KSEL)   // 7200 candidates per image

__device__ __constant__ int c_off[6] = {0, 16384, 20480, 21504, 21760, 21824};
__device__ __constant__ int c_mapS[5]   = {128, 64, 32, 16, 8};
__device__ __constant__ int c_mapOff[5] = {0, 16384, 20480, 21504, 21760};

// ---------------- device scratch ----------------
__device__ float g_relu[(size_t)174592 * 256];   // 8*21824 positions, NCHW per (b,map)
__device__ float g_wT[256 * 9 * 256];            // [ic][tap][oc]
__device__ u64   g_keys[(size_t)BB * NKEY];
__device__ u64   g_cand[(size_t)BB * NCAND];
__device__ int   g_sel[BB * KSEL];

// ---------------- f32x2 helpers ----------------
__device__ __forceinline__ void ffma2(u64 &c, u64 a, u64 b) {
    asm("fma.rn.f32x2 %0,%1,%2,%3;" : "=l"(c) : "l"(a), "l"(b), "l"(c));
}
__device__ __forceinline__ void fmul2(u64 &c, u64 a, u64 b) {
    asm("mul.rn.f32x2 %0,%1,%2;" : "=l"(c) : "l"(a), "l"(b));
}
__device__ __forceinline__ void fadd2(u64 &c, u64 a) {
    asm("add.rn.f32x2 %0,%1,%2;" : "=l"(c) : "l"(c), "l"(a));
}
__device__ __forceinline__ float2 unpack2(u64 v) {
    float2 f; asm("mov.b64 {%0,%1},%2;" : "=f"(f.x), "=f"(f.y) : "l"(v)); return f;
}

// ---------------- kernel 0: weight transpose [oc][ic][t] -> [ic][t][oc] ----------------
__global__ void k_wtrans(const float* __restrict__ w_pre) {
    int i = blockIdx.x * 1024 + threadIdx.x;
    if (i >= 256 * 9 * 256) return;
    int oc = i & 255;
    int rest = i >> 8;
    int tap = rest % 9;
    int ic = rest / 9;
    g_wT[i] = w_pre[(oc * 256 + ic) * 9 + tap];
}

// ---------------- kernel 1: conv3x3 + bias + relu ----------------
// Merged over all 5 maps. Block: 8x8 tile x 128 oc (z half). 256 threads.
// Thread: 2x2 pixels x 8 oc (4 f32x2 oc-pair regs). cp.async double-buffered.
// Inputs staged twice: raw (cp.async target) then a duplicated-pair buffer
// ([v,v] per value) so mainloop operands come straight from LDS.128 (no dup MOVs).
// Accumulation order per output: (ic 0..7, dy, dx) per chunk, 32 chunk folds;
// first write is mul.rn (== fma into 0) -> bitwise identical results.

#define IB_FLOATS 960            // 8*10*12 raw
#define ID_FLOATS 1600           // 8*10*20 duplicated pairs (10 cols x 2)
#define WB_FLOATS 9216           // 8*9*128
#define W_CHUNK_BYTES 73728      // 8*9*256*4

#define LOADROWD(dst, rr) { \
    ulonglong2 t0_ = *(const ulonglong2*)(ibd + (rr) * 20); \
    ulonglong2 t1_ = *(const ulonglong2*)(ibd + (rr) * 20 + 4); \
    dst[0] = t0_.x; dst[1] = t0_.y; dst[2] = t1_.x; dst[3] = t1_.y; }

#define TAPROW(dy, top, bot) { \
    _Pragma("unroll") \
    for (int dx = 0; dx < 3; ++dx) { \
        const ulonglong2* wp = (const ulonglong2*)(wb + ((dy)*3 + dx) * 128); \
        ulonglong2 wA = wp[0]; \
        ulonglong2 wB = wp[1]; \
        ffma2(ch[0][0], top[dx],   wA.x); ffma2(ch[0][1], top[dx],   wA.y); \
        ffma2(ch[0][2], top[dx],   wB.x); ffma2(ch[0][3], top[dx],   wB.y); \
        ffma2(ch[1][0], top[dx+1], wA.x); ffma2(ch[1][1], top[dx+1], wA.y); \
        ffma2(ch[1][2], top[dx+1], wB.x); ffma2(ch[1][3], top[dx+1], wB.y); \
        ffma2(ch[2][0], bot[dx],   wA.x); ffma2(ch[2][1], bot[dx],   wA.y); \
        ffma2(ch[2][2], bot[dx],   wB.x); ffma2(ch[2][3], bot[dx],   wB.y); \
        ffma2(ch[3][0], bot[dx+1], wA.x); ffma2(ch[3][1], bot[dx+1], wA.y); \
        ffma2(ch[3][2], bot[dx+1], wB.x); ffma2(ch[3][3], bot[dx+1], wB.y); \
    } }

// first tap row of ic 0: dx==0 initializes ch via mul (bitwise == fma into 0)
#define TAPROW0(top, bot) { \
    { \
        const ulonglong2* wp = (const ulonglong2*)(wb); \
        ulonglong2 wA = wp[0]; \
        ulonglong2 wB = wp[1]; \
        fmul2(ch[0][0], top[0], wA.x); fmul2(ch[0][1], top[0], wA.y); \
        fmul2(ch[0][2], top[0], wB.x); fmul2(ch[0][3], top[0], wB.y); \
        fmul2(ch[1][0], top[1], wA.x); fmul2(ch[1][1], top[1], wA.y); \
        fmul2(ch[1][2], top[1], wB.x); fmul2(ch[1][3], top[1], wB.y); \
        fmul2(ch[2][0], bot[0], wA.x); fmul2(ch[2][1], bot[0], wA.y); \
        fmul2(ch[2][2], bot[0], wB.x); fmul2(ch[2][3], bot[0], wB.y); \
        fmul2(ch[3][0], bot[1], wA.x); fmul2(ch[3][1], bot[1], wA.y); \
        fmul2(ch[3][2], bot[1], wB.x); fmul2(ch[3][3], bot[1], wB.y); \
    } \
    _Pragma("unroll") \
    for (int dx = 1; dx < 3; ++dx) { \
        const ulonglong2* wp = (const ulonglong2*)(wb + dx * 128); \
        ulonglong2 wA = wp[0]; \
        ulonglong2 wB = wp[1]; \
        ffma2(ch[0][0], top[dx],   wA.x); ffma2(ch[0][1], top[dx],   wA.y); \
        ffma2(ch[0][2], top[dx],   wB.x); ffma2(ch[0][3], top[dx],   wB.y); \
        ffma2(ch[1][0], top[dx+1], wA.x); ffma2(ch[1][1], top[dx+1], wA.y); \
        ffma2(ch[1][2], top[dx+1], wB.x); ffma2(ch[1][3], top[dx+1], wB.y); \
        ffma2(ch[2][0], bot[dx],   wA.x); ffma2(ch[2][1], bot[dx],   wA.y); \
        ffma2(ch[2][2], bot[dx],   wB.x); ffma2(ch[2][3], bot[dx],   wB.y); \
        ffma2(ch[3][0], bot[dx+1], wA.x); ffma2(ch[3][1], bot[dx+1], wA.y); \
        ffma2(ch[3][2], bot[dx+1], wB.x); ffma2(ch[3][3], bot[dx+1], wB.y); \
    } }

__global__ void __launch_bounds__(256, 2)
k_conv(const float* __restrict__ fm0, const float* __restrict__ fm1,
       const float* __restrict__ fm2, const float* __restrict__ fm3,
       const float* __restrict__ fm4, const float* __restrict__ b_pre) {
    extern __shared__ float sm[];
    float* ibuf[2] = {sm, sm + IB_FLOATS};
    float* in_d    = sm + 2 * IB_FLOATS;                 // 1600 floats, single-buffered
    float* wbuf[2] = {sm + 2 * IB_FLOATS + ID_FLOATS,
                      sm + 2 * IB_FLOATS + ID_FLOATS + WB_FLOATS};
    const u32 smb = (u32)__cvta_generic_to_shared(sm);
    const u32 ibs[2] = {smb, smb + IB_FLOATS * 4};
    const u32 wbs0 = smb + (2 * IB_FLOATS + ID_FLOATS) * 4;
    const u32 wbs[2] = {wbs0, wbs0 + WB_FLOATS * 4};

    const int tid = threadIdx.x;
    const int b = blockIdx.y;
    const int zh = blockIdx.z;

    // map lookup
    int bx = blockIdx.x, m, tile;
    if (bx < 256)      { m = 0; tile = bx; }
    else if (bx < 320) { m = 1; tile = bx - 256; }
    else if (bx < 336) { m = 2; tile = bx - 320; }
    else if (bx < 340) { m = 3; tile = bx - 336; }
    else               { m = 4; tile = bx - 340; }
    const int s = c_mapS[m];
    const int HW = s * s;
    const int posOff = c_mapOff[m];
    const float* fm = (m == 0) ? fm0 : (m == 1) ? fm1 : (m == 2) ? fm2 : (m == 3) ? fm3 : fm4;

    const int tilesX = s >> 3;
    const int ty0 = (tile / tilesX) << 3;
    const int tx0 = (tile % tilesX) << 3;

    const int pg = tid & 15;
    const int og = tid >> 4;              // 0..15 -> oc = zh*128 + og*8 + ..
    const int py = (pg >> 2) << 1;
    const int px = (pg & 3) << 1;

    const char* fb = (const char*)(fm + (size_t)b * 256 * HW);

    // ---- precompute cp.async + dup-pass descriptors (loop-invariant) ----
    bool in_act[4];
    u32  in_so[4], in_go[4], in_sz[4];
    u32  dp_src[4], dp_dst[4];
#pragma unroll
    for (int k = 0; k < 4; ++k) {
        int idx = tid + (k << 8);
        in_act[k] = (idx < 800);
        int ii = in_act[k] ? idx : 0;
        int ic = ii / 100;
        int rem = ii - ic * 100;
        int r = rem / 10;
        int c = rem - 10 * r;
        int gy = ty0 - 1 + r, gx = tx0 - 1 + c;
        bool ok = (gy >= 0) && (gy < s) && (gx >= 0) && (gx < s);
        in_so[k] = (u32)(((ic * 10 + r) * 12 + c) * 4);
        in_go[k] = ok ? (u32)((ic * HW + gy * s + gx) * 4) : 0u;
        in_sz[k] = ok ? 4u : 0u;
        dp_src[k] = (u32)((ic * 10 + r) * 12 + c);
        dp_dst[k] = (u32)(ic * 200 + r * 20 + c * 2);
    }
    u32 w_so[9], w_go[9];
#pragma unroll
    for (int k = 0; k < 9; ++k) {
        int i = tid + (k << 8);
        int icL = i / 288;
        int rem = i - icL * 288;
        int tap = rem >> 5;
        int q = rem & 31;
        w_so[k] = (u32)(i * 16);
        w_go[k] = (u32)(((((icL * 9 + tap) << 6) + (zh << 5) + q)) * 16);
    }
    const char* wtb = (const char*)g_wT;

    u64 acc[4][4];
#pragma unroll
    for (int p = 0; p < 4; ++p)
#pragma unroll
        for (int j = 0; j < 4; ++j) acc[p][j] = 0ull;

    // issue chunk 0
    {
#pragma unroll
        for (int k = 0; k < 4; ++k) if (in_act[k])
            asm volatile("cp.async.ca.shared.global [%0], [%1], 4, %2;"
                         :: "r"(ibs[0] + in_so[k]), "l"(fb + in_go[k]), "r"(in_sz[k]) : "memory");
#pragma unroll
        for (int k = 0; k < 9; ++k)
            asm volatile("cp.async.cg.shared.global [%0], [%1], 16;"
                         :: "r"(wbs[0] + w_so[k]), "l"(wtb + w_go[k]) : "memory");
        asm volatile("cp.async.commit_group;" ::: "memory");
    }

    const u32 inStride = (u32)(8 * HW * 4);

    for (int cc = 0; cc < 32; ++cc) {
        const int cur = cc & 1;
        asm volatile("cp.async.wait_group 0;" ::: "memory");
        __syncthreads();
        if (cc < 31) {
            const char* f = fb + (size_t)(cc + 1) * inStride;
            const char* w = wtb + (size_t)(cc + 1) * W_CHUNK_BYTES;
            const u32 ibS = ibs[cur ^ 1], wbS = wbs[cur ^ 1];
#pragma unroll
            for (int k = 0; k < 4; ++k) if (in_act[k])
                asm volatile("cp.async.ca.shared.global [%0], [%1], 4, %2;"
                             :: "r"(ibS + in_so[k]), "l"(f + in_go[k]), "r"(in_sz[k]) : "memory");
#pragma unroll
            for (int k = 0; k < 9; ++k)
                asm volatile("cp.async.cg.shared.global [%0], [%1], 16;"
                             :: "r"(wbS + w_so[k]), "l"(w + w_go[k]) : "memory");
            asm volatile("cp.async.commit_group;" ::: "memory");
        }

        // dup pass: raw -> [v,v] pairs
        {
            const float* rsrc = ibuf[cur];
#pragma unroll
            for (int k = 0; k < 4; ++k) if (in_act[k]) {
                float v = rsrc[dp_src[k]];
                *(float2*)(in_d + dp_dst[k]) = make_float2(v, v);
            }
        }
        __syncthreads();

        u64 ch[4][4];
        const float* ind_base = in_d + py * 20 + px * 2;
        const float* wbase2 = wbuf[cur] + og * 8;
        {
            const float* ibd = ind_base;
            const float* wb = wbase2;
            u64 rA[4], rB[4];
            LOADROWD(rA, 0);
            LOADROWD(rB, 1);
            TAPROW0(rA, rB);
            LOADROWD(rA, 2);
            TAPROW(1, rB, rA);
            LOADROWD(rB, 3);
            TAPROW(2, rA, rB);
        }
#pragma unroll
        for (int ic = 1; ic < 8; ++ic) {
            const float* ibd = ind_base + ic * 200;
            const float* wb = wbase2 + ic * 1152;
            u64 rA[4], rB[4];
            LOADROWD(rA, 0);
            LOADROWD(rB, 1);
            TAPROW(0, rA, rB);
            LOADROWD(rA, 2);
            TAPROW(1, rB, rA);
            LOADROWD(rB, 3);
            TAPROW(2, rA, rB);
        }
#pragma unroll
        for (int p = 0; p < 4; ++p)
#pragma unroll
            for (int j = 0; j < 4; ++j) fadd2(acc[p][j], ch[p][j]);
    }

    // epilogue: bias + relu -> g_relu NCHW per (b,map)
    float* outB = g_relu + ((size_t)b * NPOS + posOff) * 256;
#pragma unroll
    for (int p = 0; p < 4; ++p) {
        int gy = ty0 + py + (p >> 1);
        int gx = tx0 + px + (p & 1);
#pragma unroll
        for (int j = 0; j < 4; ++j) {
            int oc = zh * 128 + og * 8 + 2 * j;
            float2 v = unpack2(acc[p][j]);
            outB[(size_t)oc * HW + gy * s + gx]       = fmaxf(v.x + b_pre[oc], 0.f);
            outB[(size_t)(oc + 1) * HW + gy * s + gx] = fmaxf(v.y + b_pre[oc + 1], 0.f);
        }
    }
}

// ---------------- kernel 2: 1x1 proj -> sigmoid -> sortable keys ----------------
__global__ void __launch_bounds__(256)
k_proj(const float* __restrict__ w_proj, const float* __restrict__ b_proj) {
    __shared__ float ws[9 * 256];
    const int tid = threadIdx.x;
    for (int i = tid; i < 2304; i += 256) ws[i] = w_proj[i];
    __syncthreads();

    const int b = blockIdx.y;
    const int p = blockIdx.x * 256 + tid;

    if (blockIdx.x == 0 && tid < (NKEY - NANCH))
        g_keys[(size_t)b * NKEY + NANCH + tid] = 0ull;
    if (p >= NPOS) return;

    int m, hw, HW;
    if (p < 16384)      { m = 0; hw = p;         HW = 16384; }
    else if (p < 20480) { m = 1; hw = p - 16384; HW = 4096;  }
    else if (p < 21504) { m = 2; hw = p - 20480; HW = 1024;  }
    else if (p < 21760) { m = 3; hw = p - 21504; HW = 256;   }
    else                { m = 4; hw = p - 21760; HW = 64;    }
    const int off = c_off[m];

    const float* rb = g_relu + ((size_t)b * NPOS + off) * 256 + hw;
    float sum[9];
#pragma unroll
    for (int a = 0; a < 9; ++a) sum[a] = 0.f;
    for (int c0 = 0; c0 < 256; c0 += 32) {
        float cs[9];
#pragma unroll
        for (int a = 0; a < 9; ++a) cs[a] = 0.f;
        for (int c = c0; c < c0 + 32; ++c) {
            float v = rb[(size_t)c * HW];
#pragma unroll
            for (int a = 0; a < 9; ++a) cs[a] += v * ws[a * 256 + c];
        }
#pragma unroll
        for (int a = 0; a < 9; ++a) sum[a] += cs[a];
    }
    u64* kb = g_keys + (size_t)b * NKEY + (size_t)p * 9;
#pragma unroll
    for (int a = 0; a < 9; ++a) {
        float logit = sum[a] + b_proj[a];
        float prob = 1.0f / (1.0f + expf(-logit));
        u32 pb = __float_as_uint(prob);
        u32 idx = (u32)(p * 9 + a);
        kb[a] = ((u64)pb << 32) | (u64)(0xFFFFFFFFu - idx);
    }
}

// ---------------- bitonic helpers (descending) ----------------
__device__ __forceinline__ void bitonic_step(u64* sk, int i, int j, int k) {
    int ixj = i | j;
    u64 a = sk[i], b = sk[ixj];
    bool dir = ((i & k) == 0);
    bool sw = dir ? (a < b) : (a > b);
    if (sw) { sk[i] = b; sk[ixj] = a; }
}

// ---------------- kernel 3: stage1 — sort each 8192 chunk, keep top 300 ----------------
__global__ void __launch_bounds__(1024)
k_top1() {
    extern __shared__ u64 sk[];      // 8192 keys = 64KB
    const int tid = threadIdx.x;
    const int blk = blockIdx.x;
    const int b = blockIdx.y;
    const u64* src = g_keys + (size_t)b * NKEY + (size_t)blk * 8192;
    for (int i = tid; i < 8192; i += 1024) sk[i] = src[i];
    for (int k = 2; k <= 8192; k <<= 1) {
        for (int j = k >> 1; j > 0; j >>= 1) {
            __syncthreads();
            for (int t = tid; t < 4096; t += 1024) {
                int i = ((t & ~(j - 1)) << 1) | (t & (j - 1));
                bitonic_step(sk, i, j, k);
            }
        }
    }
    __syncthreads();
    u64* dst = g_cand + ((size_t)b * NCHUNK + blk) * KSEL;
    for (int i = tid; i < KSEL; i += 1024) dst[i] = sk[i];
}

// ---------------- kernel 4: stage2 — merge 7200 candidates per image ----------------
__global__ void __launch_bounds__(1024)
k_top2() {
    extern __shared__ u64 sk2[];     // 8192 keys = 64KB
    const int tid = threadIdx.x;
    const int b = blockIdx.x;
    const u64* src = g_cand + (size_t)b * NCAND;
    for (int i = tid; i < 8192; i += 1024) sk2[i] = (i < NCAND) ? src[i] : 0ull;
    for (int k = 2; k <= 8192; k <<= 1) {
        for (int j = k >> 1; j > 0; j >>= 1) {
            __syncthreads();
            for (int t = tid; t < 4096; t += 1024) {
                int i = ((t & ~(j - 1)) << 1) | (t & (j - 1));
                bitonic_step(sk2, i, j, k);
            }
        }
    }
    __syncthreads();
    if (tid < KSEL)
        g_sel[b * KSEL + tid] = (int)(0xFFFFFFFFu - (u32)(sk2[tid] & 0xFFFFFFFFull));
}

// ---------------- kernel 5: gather features + per-anchor 256x256 matvec ----------------
__global__ void __launch_bounds__(256)
k_post(const float* __restrict__ fm0, const float* __restrict__ fm1,
       const float* __restrict__ fm2, const float* __restrict__ fm3,
       const float* __restrict__ fm4, const float* __restrict__ w_post,
       const float* __restrict__ b_post, float* __restrict__ out) {
    __shared__ float x[256];
    const int n = blockIdx.x;
    const int tid = threadIdx.x;
    const int b = n / KSEL;
    const int anchor = g_sel[n];
    const int pos = anchor / 9;
    const int a = anchor - 9 * (anchor / 9);

    int m, hw, HW;
    if (pos < 16384)      { m = 0; hw = pos;         HW = 16384; }
    else if (pos < 20480) { m = 1; hw = pos - 16384; HW = 4096;  }
    else if (pos < 21504) { m = 2; hw = pos - 20480; HW = 1024;  }
    else if (pos < 21760) { m = 3; hw = pos - 21504; HW = 256;   }
    else                  { m = 4; hw = pos - 21760; HW = 64;    }
    const float* fm = (m == 0) ? fm0 : (m == 1) ? fm1 : (m == 2) ? fm2 : (m == 3) ? fm3 : fm4;

    x[tid] = fm[((size_t)b * 256 + tid) * HW + hw];
    __syncthreads();

    const float* W = w_post + (size_t)a * 65536;
    float accv = b_post[a * 256 + tid];
#pragma unroll 8
    for (int d = 0; d < 256; ++d)
        accv += x[d] * W[d * 256 + tid];
    out[(size_t)n * 256 + tid] = accv;
}

// ---------------- launch ----------------
extern "C" void kernel_launch(void* const* d_in, const int* in_sizes, int n_in,
                              void* d_out, int out_size) {
    const float* fm[5];
    for (int i = 0; i < 5; ++i) fm[i] = (const float*)d_in[i];
    const float* w_pre  = (const float*)d_in[5];
    const float* b_pre  = (const float*)d_in[6];
    const float* w_proj = (const float*)d_in[7];
    const float* b_proj = (const float*)d_in[8];
    const float* w_post = (const float*)d_in[9];
    const float* b_post = (const float*)d_in[10];
    float* out = (float*)d_out;

    const int convSmem = (2 * IB_FLOATS + ID_FLOATS + 2 * WB_FLOATS) * 4;  // 87808 B
    cudaFuncSetAttribute(k_conv, cudaFuncAttributeMaxDynamicSharedMemorySize, convSmem);
    cudaFuncSetAttribute(k_top1, cudaFuncAttributeMaxDynamicSharedMemorySize, 8192 * 8);
    cudaFuncSetAttribute(k_top2, cudaFuncAttributeMaxDynamicSharedMemorySize, 8192 * 8);

    k_wtrans<<<576, 1024>>>(w_pre);

    {
        dim3 grid(341, BB, 2);   // 256+64+16+4+1 tiles across 5 maps
        k_conv<<<grid, 256, convSmem>>>(fm[0], fm[1], fm[2], fm[3], fm[4], b_pre);
    }
    {
        dim3 grid((NPOS + 255) / 256, BB);
        k_proj<<<grid, 256>>>(w_proj, b_proj);
    }
    {
        dim3 grid(NCHUNK, BB);
        k_top1<<<grid, 1024, 8192 * 8>>>();
    }
    k_top2<<<BB, 1024, 8192 * 8>>>();
    k_post<<<BB * KSEL, 256>>>(fm[0], fm[1], fm[2], fm[3], fm[4], w_post, b_post, out);
}

// round 7
// speedup vs baseline: 1.4450x; 1.4450x over previous
#include <cuda_runtime.h>
#include <cstdint>

typedef unsigned long long u64;
typedef unsigned int u32;

// ---------------- problem constants ----------------
#define BB 8
#define CC 256
#define NPOS 21824              // per-image positions across 5 maps
#define NANCH 196416            // NPOS * 9
#define NKEY 196608             // 48 * 4096 (padded)
#define KSEL 300
#define NCHUNK 48               // stage1 chunks of 4096 per image
#define NCAND (NCHUNK * KSEL)   // 14400 candidates per image
#define NLOGIT (BB * NPOS * 9)  // 1571328

__device__ __constant__ int c_mapS[5]   = {128, 64, 32, 16, 8};
__device__ __constant__ int c_mapOff[5] = {0, 16384, 20480, 21504, 21760};

// ---------------- device scratch ----------------
__device__ float g_wT[256 * 9 * 256];            // [ic][tap][oc]
__device__ float g_logits[(size_t)NLOGIT];       // fused proj output (atomic 2-way)
__device__ u64   g_keys[(size_t)BB * NKEY];
__device__ u64   g_cand[(size_t)BB * NCAND];
__device__ int   g_sel[BB * KSEL];

// ---------------- f32x2 helpers ----------------
__device__ __forceinline__ u64 dup2(float x) {
    u64 r; asm("mov.b64 %0,{%1,%1};" : "=l"(r) : "f"(x)); return r;
}
__device__ __forceinline__ void ffma2(u64 &c, u64 a, u64 b) {
    asm("fma.rn.f32x2 %0,%1,%2,%3;" : "=l"(c) : "l"(a), "l"(b), "l"(c));
}
__device__ __forceinline__ void fadd2(u64 &c, u64 a) {
    asm("add.rn.f32x2 %0,%1,%2;" : "=l"(c) : "l"(c), "l"(a));
}
__device__ __forceinline__ float2 unpack2(u64 v) {
    float2 f; asm("mov.b64 {%0,%1},%2;" : "=f"(f.x), "=f"(f.y) : "l"(v)); return f;
}

// ---------------- kernel 0a: zero logits + key padding (every replay) ----------------
__global__ void k_init() {
    int i = blockIdx.x * 1024 + threadIdx.x;
    if (i < NLOGIT) g_logits[i] = 0.f;
    if (i < BB * (NKEY - NANCH)) {
        int b = i / (NKEY - NANCH);
        int r = i - b * (NKEY - NANCH);
        g_keys[(size_t)b * NKEY + NANCH + r] = 0ull;
    }
}

// ---------------- kernel 0b: weight transpose [oc][ic][t] -> [ic][t][oc] ----------------
__global__ void k_wtrans(const float* __restrict__ w_pre) {
    int i = blockIdx.x * 1024 + threadIdx.x;
    if (i >= 256 * 9 * 256) return;
    int oc = i & 255;
    int rest = i >> 8;
    int tap = rest % 9;
    int ic = rest / 9;
    g_wT[i] = w_pre[(oc * 256 + ic) * 9 + tap];
}

// ---------------- kernel 1: conv3x3 + bias + relu + FUSED 1x1 proj ----------------
// Merged over all 5 maps. Block: 8x8 tile x 128 oc (z half). 256 threads.
// Thread: 2x2 pixels x 8 oc (4 f32x2 oc-pair regs). cp.async double-buffered.
// Mainloop identical to the 3952us passing kernel (bitwise-identical relu values).
// Epilogue: per-thread proj partials (oc ascending), og-tree reduction in fixed
// order through smem, 2-way atomicAdd (commutative -> deterministic) into g_logits.

#define IB_FLOATS 960            // 8*10*12
#define WB_FLOATS 9216           // 8*9*128
#define W_CHUNK_BYTES 73728      // 8*9*256*4

#define LOADROW(dst, rr) { \
    float2 a_ = *(const float2*)(ib + (rr)*12); \
    float2 b_ = *(const float2*)(ib + (rr)*12 + 2); \
    dst[0] = dup2(a_.x); dst[1] = dup2(a_.y); \
    dst[2] = dup2(b_.x); dst[3] = dup2(b_.y); }

#define TAPROW(dy, top, bot) { \
    _Pragma("unroll") \
    for (int dx = 0; dx < 3; ++dx) { \
        const ulonglong2* wp = (const ulonglong2*)(wb + ((dy)*3 + dx) * 128); \
        ulonglong2 wA = wp[0]; \
        ulonglong2 wB = wp[1]; \
        ffma2(ch[0][0], top[dx],   wA.x); ffma2(ch[0][1], top[dx],   wA.y); \
        ffma2(ch[0][2], top[dx],   wB.x); ffma2(ch[0][3], top[dx],   wB.y); \
        ffma2(ch[1][0], top[dx+1], wA.x); ffma2(ch[1][1], top[dx+1], wA.y); \
        ffma2(ch[1][2], top[dx+1], wB.x); ffma2(ch[1][3], top[dx+1], wB.y); \
        ffma2(ch[2][0], bot[dx],   wA.x); ffma2(ch[2][1], bot[dx],   wA.y); \
        ffma2(ch[2][2], bot[dx],   wB.x); ffma2(ch[2][3], bot[dx],   wB.y); \
        ffma2(ch[3][0], bot[dx+1], wA.x); ffma2(ch[3][1], bot[dx+1], wA.y); \
        ffma2(ch[3][2], bot[dx+1], wB.x); ffma2(ch[3][3], bot[dx+1], wB.y); \
    } }

__global__ void __launch_bounds__(256, 2)
k_conv(const float* __restrict__ fm0, const float* __restrict__ fm1,
       const float* __restrict__ fm2, const float* __restrict__ fm3,
       const float* __restrict__ fm4, const float* __restrict__ b_pre,
       const float* __restrict__ w_proj) {
    extern __shared__ float sm[];
    float* ibuf[2] = {sm, sm + IB_FLOATS};
    float* wbuf[2] = {sm + 2 * IB_FLOATS, sm + 2 * IB_FLOATS + WB_FLOATS};
    const u32 smb = (u32)__cvta_generic_to_shared(sm);
    const u32 ibs[2] = {smb, smb + IB_FLOATS * 4};
    const u32 wbs[2] = {smb + 2 * IB_FLOATS * 4, smb + 2 * IB_FLOATS * 4 + WB_FLOATS * 4};

    const int tid = threadIdx.x;
    const int b = blockIdx.y;
    const int zh = blockIdx.z;

    // map lookup
    int bx = blockIdx.x, m, tile;
    if (bx < 256)      { m = 0; tile = bx; }
    else if (bx < 320) { m = 1; tile = bx - 256; }
    else if (bx < 336) { m = 2; tile = bx - 320; }
    else if (bx < 340) { m = 3; tile = bx - 336; }
    else               { m = 4; tile = bx - 340; }
    const int s = c_mapS[m];
    const int HW = s * s;
    const int posOff = c_mapOff[m];
    const float* fm = (m == 0) ? fm0 : (m == 1) ? fm1 : (m == 2) ? fm2 : (m == 3) ? fm3 : fm4;

    const int tilesX = s >> 3;
    const int ty0 = (tile / tilesX) << 3;
    const int tx0 = (tile % tilesX) << 3;

    const int pg = tid & 15;
    const int og = tid >> 4;              // 0..15 -> oc = zh*128 + og*8 + ..
    const int py = (pg >> 2) << 1;
    const int px = (pg & 3) << 1;

    const char* fb = (const char*)(fm + (size_t)b * 256 * HW);

    // ---- precompute cp.async descriptors (loop-invariant) ----
    bool in_act[4];
    u32  in_so[4], in_go[4], in_sz[4];
#pragma unroll
    for (int k = 0; k < 4; ++k) {
        int idx = tid + (k << 8);
        in_act[k] = (idx < 800);
        int ii = in_act[k] ? idx : 0;
        int ic = ii / 100;
        int rem = ii - ic * 100;
        int r = rem / 10;
        int c = rem - 10 * r;
        int gy = ty0 - 1 + r, gx = tx0 - 1 + c;
        bool ok = (gy >= 0) && (gy < s) && (gx >= 0) && (gx < s);
        in_so[k] = (u32)(((ic * 10 + r) * 12 + c) * 4);
        in_go[k] = ok ? (u32)((ic * HW + gy * s + gx) * 4) : 0u;
        in_sz[k] = ok ? 4u : 0u;
    }
    u32 w_so[9], w_go[9];
#pragma unroll
    for (int k = 0; k < 9; ++k) {
        int i = tid + (k << 8);
        int icL = i / 288;
        int rem = i - icL * 288;
        int tap = rem >> 5;
        int q = rem & 31;
        w_so[k] = (u32)(i * 16);
        w_go[k] = (u32)(((((icL * 9 + tap) << 6) + (zh << 5) + q)) * 16);
    }
    const char* wtb = (const char*)g_wT;

    u64 acc[4][4];
#pragma unroll
    for (int p = 0; p < 4; ++p)
#pragma unroll
        for (int j = 0; j < 4; ++j) acc[p][j] = 0ull;

    // issue chunk 0
    {
#pragma unroll
        for (int k = 0; k < 4; ++k) if (in_act[k])
            asm volatile("cp.async.ca.shared.global [%0], [%1], 4, %2;"
                         :: "r"(ibs[0] + in_so[k]), "l"(fb + in_go[k]), "r"(in_sz[k]) : "memory");
#pragma unroll
        for (int k = 0; k < 9; ++k)
            asm volatile("cp.async.cg.shared.global [%0], [%1], 16;"
                         :: "r"(wbs[0] + w_so[k]), "l"(wtb + w_go[k]) : "memory");
        asm volatile("cp.async.commit_group;" ::: "memory");
    }

    const u32 inStride = (u32)(8 * HW * 4);

    for (int cc = 0; cc < 32; ++cc) {
        const int cur = cc & 1;
        asm volatile("cp.async.wait_group 0;" ::: "memory");
        __syncthreads();
        if (cc < 31) {
            const char* f = fb + (size_t)(cc + 1) * inStride;
            const char* w = wtb + (size_t)(cc + 1) * W_CHUNK_BYTES;
            const u32 ibS = ibs[cur ^ 1], wbS = wbs[cur ^ 1];
#pragma unroll
            for (int k = 0; k < 4; ++k) if (in_act[k])
                asm volatile("cp.async.ca.shared.global [%0], [%1], 4, %2;"
                             :: "r"(ibS + in_so[k]), "l"(f + in_go[k]), "r"(in_sz[k]) : "memory");
#pragma unroll
            for (int k = 0; k < 9; ++k)
                asm volatile("cp.async.cg.shared.global [%0], [%1], 16;"
                             :: "r"(wbS + w_so[k]), "l"(w + w_go[k]) : "memory");
            asm volatile("cp.async.commit_group;" ::: "memory");
        }

        u64 ch[4][4];
#pragma unroll
        for (int p = 0; p < 4; ++p)
#pragma unroll
            for (int j = 0; j < 4; ++j) ch[p][j] = 0ull;

        const float* ibase = ibuf[cur] + py * 12 + px;
        const float* wbase2 = wbuf[cur] + og * 8;
#pragma unroll
        for (int ic = 0; ic < 8; ++ic) {
            const float* ib = ibase + ic * 120;
            const float* wb = wbase2 + ic * 1152;
            u64 rA[4], rB[4];
            LOADROW(rA, 0);
            LOADROW(rB, 1);
            TAPROW(0, rA, rB);
            LOADROW(rA, 2);
            TAPROW(1, rB, rA);
            LOADROW(rB, 3);
            TAPROW(2, rA, rB);
        }
#pragma unroll
        for (int p = 0; p < 4; ++p)
#pragma unroll
            for (int j = 0; j < 4; ++j) fadd2(acc[p][j], ch[p][j]);
    }

    // ---- fused epilogue: bias + relu + 1x1 proj partials ----
    // Per-thread: 4 pixels x 9 anchors, summed over this thread's 8 ocs (ascending).
    float part[4][9];
#pragma unroll
    for (int p = 0; p < 4; ++p)
#pragma unroll
        for (int a = 0; a < 9; ++a) part[p][a] = 0.f;

#pragma unroll
    for (int j = 0; j < 4; ++j) {
        const int oc = zh * 128 + og * 8 + 2 * j;
        const float b0 = b_pre[oc], b1 = b_pre[oc + 1];
#pragma unroll
        for (int p = 0; p < 4; ++p) {
            float2 v = unpack2(acc[p][j]);
            float r0 = fmaxf(v.x + b0, 0.f);
            float r1 = fmaxf(v.y + b1, 0.f);
#pragma unroll
            for (int a = 0; a < 9; ++a) {
                float t = part[p][a];
                t = fmaf(r0, w_proj[a * 256 + oc], t);
                t = fmaf(r1, w_proj[a * 256 + oc + 1], t);
                part[p][a] = t;
            }
        }
    }

    // stage partials to smem: layout [og][pixel(64)][anchor(9)] in wbuf[0] (9216 floats)
    // wbuf[0] held chunk-30 weights; all reads of it finished before chunk-31 compute.
    float* red = wbuf[0];
#pragma unroll
    for (int p = 0; p < 4; ++p) {
        int pl = (py + (p >> 1)) * 8 + (px + (p & 1));
#pragma unroll
        for (int a = 0; a < 9; ++a)
            red[(og * 64 + pl) * 9 + a] = part[p][a];
    }
    __syncthreads();

    // reduce over og in fixed ascending order -> atomicAdd (2 contributions/logit)
    for (int item = tid; item < 576; item += 256) {
        int pl = item / 9;
        int a = item - 9 * pl;
        float v = 0.f;
#pragma unroll
        for (int o = 0; o < 16; ++o)
            v += red[(o * 64 + pl) * 9 + a];
        int gy = ty0 + (pl >> 3);
        int gx = tx0 + (pl & 7);
        int pos = posOff + gy * s + gx;
        atomicAdd(&g_logits[((size_t)b * NPOS + pos) * 9 + a], v);
    }
}

// ---------------- kernel 2: logits -> sigmoid -> sortable keys ----------------
__global__ void __launch_bounds__(256)
k_keys(const float* __restrict__ b_proj) {
    int gid = blockIdx.x * 256 + threadIdx.x;
    if (gid >= BB * NPOS) return;
    int b = gid / NPOS;
    int p = gid - b * NPOS;
    const float* lg = g_logits + (size_t)gid * 9;
    u64* kb = g_keys + (size_t)b * NKEY + (size_t)p * 9;
#pragma unroll
    for (int a = 0; a < 9; ++a) {
        float logit = lg[a] + b_proj[a];
        float prob = 1.0f / (1.0f + expf(-logit));
        u32 pb = __float_as_uint(prob);                 // prob>0 => bit-monotonic
        u32 idx = (u32)(p * 9 + a);
        kb[a] = ((u64)pb << 32) | (u64)(0xFFFFFFFFu - idx);  // tie -> lower idx first
    }
}

// ---------------- bitonic helpers (descending) ----------------
__device__ __forceinline__ void bitonic_step(u64* sk, int i, int j, int k) {
    int ixj = i | j;
    u64 a = sk[i], b = sk[ixj];
    bool dir = ((i & k) == 0);
    bool sw = dir ? (a < b) : (a > b);
    if (sw) { sk[i] = b; sk[ixj] = a; }
}

// ---------------- kernel 3: stage1 — sort each 4096 chunk, keep top 300 ----------------
__global__ void __launch_bounds__(512)
k_top1() {
    __shared__ u64 sk[4096];
    const int tid = threadIdx.x;
    const int blk = blockIdx.x;
    const int b = blockIdx.y;
    const u64* src = g_keys + (size_t)b * NKEY + (size_t)blk * 4096;
    for (int i = tid; i < 4096; i += 512) sk[i] = src[i];
    for (int k = 2; k <= 4096; k <<= 1) {
        for (int j = k >> 1; j > 0; j >>= 1) {
            __syncthreads();
            for (int t = tid; t < 2048; t += 512) {
                int i = ((t & ~(j - 1)) << 1) | (t & (j - 1));
                bitonic_step(sk, i, j, k);
            }
        }
    }
    __syncthreads();
    u64* dst = g_cand + ((size_t)b * NCHUNK + blk) * KSEL;
    for (int i = tid; i < KSEL; i += 512) dst[i] = sk[i];
}

// ---------------- kernel 4: stage2 — merge 14400 candidates per image ----------------
__global__ void __launch_bounds__(1024)
k_top2() {
    extern __shared__ u64 sk2[];   // 16384 keys = 128KB
    const int tid = threadIdx.x;
    const int b = blockIdx.x;
    const u64* src = g_cand + (size_t)b * NCAND;
    for (int i = tid; i < 16384; i += 1024) sk2[i] = (i < NCAND) ? src[i] : 0ull;
    for (int k = 2; k <= 16384; k <<= 1) {
        for (int j = k >> 1; j > 0; j >>= 1) {
            __syncthreads();
            for (int t = tid; t < 8192; t += 1024) {
                int i = ((t & ~(j - 1)) << 1) | (t & (j - 1));
                bitonic_step(sk2, i, j, k);
            }
        }
    }
    __syncthreads();
    if (tid < KSEL)
        g_sel[b * KSEL + tid] = (int)(0xFFFFFFFFu - (u32)(sk2[tid] & 0xFFFFFFFFull));
}

// ---------------- kernel 5: gather features + per-anchor 256x256 matvec ----------------
__global__ void __launch_bounds__(256)
k_post(const float* __restrict__ fm0, const float* __restrict__ fm1,
       const float* __restrict__ fm2, const float* __restrict__ fm3,
       const float* __restrict__ fm4, const float* __restrict__ w_post,
       const float* __restrict__ b_post, float* __restrict__ out) {
    __shared__ float x[256];
    const int n = blockIdx.x;
    const int tid = threadIdx.x;
    const int b = n / KSEL;
    const int anchor = g_sel[n];
    const int pos = anchor / 9;
    const int a = anchor - 9 * (anchor / 9);

    int m, hw, HW;
    if (pos < 16384)      { m = 0; hw = pos;         HW = 16384; }
    else if (pos < 20480) { m = 1; hw = pos - 16384; HW = 4096;  }
    else if (pos < 21504) { m = 2; hw = pos - 20480; HW = 1024;  }
    else if (pos < 21760) { m = 3; hw = pos - 21504; HW = 256;   }
    else                  { m = 4; hw = pos - 21760; HW = 64;    }
    const float* fm = (m == 0) ? fm0 : (m == 1) ? fm1 : (m == 2) ? fm2 : (m == 3) ? fm3 : fm4;

    x[tid] = fm[((size_t)b * 256 + tid) * HW + hw];
    __syncthreads();

    const float* W = w_post + (size_t)a * 65536;
    float accv = b_post[a * 256 + tid];
#pragma unroll 8
    for (int d = 0; d < 256; ++d)
        accv += x[d] * W[d * 256 + tid];
    out[(size_t)n * 256 + tid] = accv;
}

// ---------------- launch ----------------
extern "C" void kernel_launch(void* const* d_in, const int* in_sizes, int n_in,
                              void* d_out, int out_size) {
    const float* fm[5];
    for (int i = 0; i < 5; ++i) fm[i] = (const float*)d_in[i];
    const float* w_pre  = (const float*)d_in[5];
    const float* b_pre  = (const float*)d_in[6];
    const float* w_proj = (const float*)d_in[7];
    const float* b_proj = (const float*)d_in[8];
    const float* w_post = (const float*)d_in[9];
    const float* b_post = (const float*)d_in[10];
    float* out = (float*)d_out;

    const int convSmem = (2 * IB_FLOATS + 2 * WB_FLOATS) * 4;   // 81408 B
    cudaFuncSetAttribute(k_conv, cudaFuncAttributeMaxDynamicSharedMemorySize, convSmem);
    cudaFuncSetAttribute(k_top2, cudaFuncAttributeMaxDynamicSharedMemorySize, 16384 * 8);

    k_init<<<(NLOGIT + 1023) / 1024, 1024>>>();
    k_wtrans<<<576, 1024>>>(w_pre);

    {
        dim3 grid(341, BB, 2);   // 256+64+16+4+1 tiles across 5 maps
        k_conv<<<grid, 256, convSmem>>>(fm[0], fm[1], fm[2], fm[3], fm[4], b_pre, w_proj);
    }
    k_keys<<<(BB * NPOS + 255) / 256, 256>>>(b_proj);
    {
        dim3 grid(NCHUNK, BB);
        k_top1<<<grid, 512>>>();
    }
    k_top2<<<BB, 1024, 16384 * 8>>>();
    k_post<<<BB * KSEL, 256>>>(fm[0], fm[1], fm[2], fm[3], fm[4], w_post, b_post, out);
}